// round 1
// baseline (speedup 1.0000x reference)
#include <cuda_runtime.h>
#include <math.h>

// Problem constants
#define BT_ROWS 1024     // B*T
#define KDIM    256
#define TSEQ    512
#define VDIM    32000
#define INNERD  512
#define NBATCH  2
#define SPARSE_K 128
#define EPS_F   1.1920929e-7f

// ---------------- scratch (static device allocations) ----------------
__device__ __align__(16) float d_gathered[BT_ROWS * KDIM];
__device__ __align__(16) float d_gn1[BT_ROWS * KDIM];
__device__ __align__(16) float d_q[BT_ROWS * KDIM];
__device__ __align__(16) float d_kk[BT_ROWS * KDIM];
__device__ __align__(16) float d_v[BT_ROWS * KDIM];
__device__ __align__(16) float d_scores[NBATCH * TSEQ * TSEQ];
__device__ __align__(16) float d_retr[BT_ROWS * KDIM];
__device__ __align__(16) float d_g2[BT_ROWS * KDIM];
__device__ __align__(16) float d_gn2[BT_ROWS * KDIM];
__device__ __align__(16) float d_h[BT_ROWS * INNERD];
__device__ __align__(16) float d_mlp[BT_ROWS * KDIM];

// ---------------- GEMM cores: 64x64 block, 256 threads, 4x4 micro ----------------
// C = A (MxK, row-major) * B^T (B is NxK row-major)
__device__ __forceinline__ void gemm_nt_core(
    const float* __restrict__ A, const float* __restrict__ B,
    int K, int m0, int n0, float acc[4][4])
{
    __shared__ __align__(16) float As[16][64];
    __shared__ __align__(16) float Bs[16][64];
    const int tid  = threadIdx.x;
    const int lrow = tid >> 2;      // 0..63
    const int lc4  = tid & 3;       // 0..3 (float4 group within 16 cols)
    const int tx   = tid & 15;
    const int ty   = tid >> 4;

#pragma unroll
    for (int i = 0; i < 4; i++)
#pragma unroll
        for (int j = 0; j < 4; j++) acc[i][j] = 0.f;

    for (int k0 = 0; k0 < K; k0 += 16) {
        float4 a = *(const float4*)&A[(size_t)(m0 + lrow) * K + k0 + lc4 * 4];
        float4 b = *(const float4*)&B[(size_t)(n0 + lrow) * K + k0 + lc4 * 4];
        As[lc4 * 4 + 0][lrow] = a.x; As[lc4 * 4 + 1][lrow] = a.y;
        As[lc4 * 4 + 2][lrow] = a.z; As[lc4 * 4 + 3][lrow] = a.w;
        Bs[lc4 * 4 + 0][lrow] = b.x; Bs[lc4 * 4 + 1][lrow] = b.y;
        Bs[lc4 * 4 + 2][lrow] = b.z; Bs[lc4 * 4 + 3][lrow] = b.w;
        __syncthreads();
#pragma unroll
        for (int kkk = 0; kkk < 16; ++kkk) {
            float4 av = *(const float4*)&As[kkk][ty * 4];
            float4 bv = *(const float4*)&Bs[kkk][tx * 4];
            float ar[4] = {av.x, av.y, av.z, av.w};
            float br[4] = {bv.x, bv.y, bv.z, bv.w};
#pragma unroll
            for (int i = 0; i < 4; i++)
#pragma unroll
                for (int j = 0; j < 4; j++) acc[i][j] += ar[i] * br[j];
        }
        __syncthreads();
    }
}

// C = A (MxK, row-major, lda=K) * B (KxN row-major). kstart: skip leading k-tiles.
__device__ __forceinline__ void gemm_nn_core(
    const float* __restrict__ A, const float* __restrict__ B,
    int K, int N, int m0, int n0, int kstart, float acc[4][4])
{
    __shared__ __align__(16) float As[16][64];
    __shared__ __align__(16) float Bs[16][64];
    const int tid  = threadIdx.x;
    const int lrow = tid >> 2;
    const int lc4  = tid & 3;
    const int brow = tid >> 4;      // 0..15
    const int bc4  = tid & 15;      // 0..15
    const int tx   = tid & 15;
    const int ty   = tid >> 4;

#pragma unroll
    for (int i = 0; i < 4; i++)
#pragma unroll
        for (int j = 0; j < 4; j++) acc[i][j] = 0.f;

    for (int k0 = kstart; k0 < K; k0 += 16) {
        float4 a = *(const float4*)&A[(size_t)(m0 + lrow) * K + k0 + lc4 * 4];
        As[lc4 * 4 + 0][lrow] = a.x; As[lc4 * 4 + 1][lrow] = a.y;
        As[lc4 * 4 + 2][lrow] = a.z; As[lc4 * 4 + 3][lrow] = a.w;
        float4 b = *(const float4*)&B[(size_t)(k0 + brow) * N + n0 + bc4 * 4];
        *(float4*)&Bs[brow][bc4 * 4] = b;
        __syncthreads();
#pragma unroll
        for (int kkk = 0; kkk < 16; ++kkk) {
            float4 av = *(const float4*)&As[kkk][ty * 4];
            float4 bv = *(const float4*)&Bs[kkk][tx * 4];
            float ar[4] = {av.x, av.y, av.z, av.w};
            float br[4] = {bv.x, bv.y, bv.z, bv.w};
#pragma unroll
            for (int i = 0; i < 4; i++)
#pragma unroll
                for (int j = 0; j < 4; j++) acc[i][j] += ar[i] * br[j];
        }
        __syncthreads();
    }
}

// ---------------- stage kernels ----------------

// gather x[:, :, read_idx] -> gathered, rmsnorm -> gn1
__global__ void k_gather_rms(const float* __restrict__ x, const int* __restrict__ ridx)
{
    const int row = blockIdx.x;
    const int tid = threadIdx.x;
    float g = x[(size_t)row * VDIM + ridx[tid]];
    d_gathered[row * KDIM + tid] = g;
    __shared__ float red[8];
    float s = g * g;
#pragma unroll
    for (int o = 16; o; o >>= 1) s += __shfl_xor_sync(0xffffffffu, s, o);
    if ((tid & 31) == 0) red[tid >> 5] = s;
    __syncthreads();
    if (tid < 32) {
        float v = (tid < 8) ? red[tid] : 0.f;
#pragma unroll
        for (int o = 4; o; o >>= 1) v += __shfl_xor_sync(0xffffffffu, v, o);
        if (tid == 0) red[0] = v;
    }
    __syncthreads();
    float r = rsqrtf(red[0] * (1.f / KDIM) + EPS_F);
    d_gn1[row * KDIM + tid] = g * r;
}

// rmsnorm g2 -> gn2
__global__ void k_rms2()
{
    const int row = blockIdx.x;
    const int tid = threadIdx.x;
    float g = d_g2[row * KDIM + tid];
    __shared__ float red[8];
    float s = g * g;
#pragma unroll
    for (int o = 16; o; o >>= 1) s += __shfl_xor_sync(0xffffffffu, s, o);
    if ((tid & 31) == 0) red[tid >> 5] = s;
    __syncthreads();
    if (tid < 32) {
        float v = (tid < 8) ? red[tid] : 0.f;
#pragma unroll
        for (int o = 4; o; o >>= 1) v += __shfl_xor_sync(0xffffffffu, v, o);
        if (tid == 0) red[0] = v;
    }
    __syncthreads();
    float r = rsqrtf(red[0] * (1.f / KDIM) + EPS_F);
    d_gn2[row * KDIM + tid] = g * r;
}

// q,k,v = gn1 @ W{q,k,v}^T   grid(4,16,3)
__global__ void k_qkv(const float* __restrict__ Wq, const float* __restrict__ Wk,
                      const float* __restrict__ Wv)
{
    const int m0 = blockIdx.y * 64, n0 = blockIdx.x * 64;
    const float* W = (blockIdx.z == 0) ? Wq : (blockIdx.z == 1) ? Wk : Wv;
    float* C = (blockIdx.z == 0) ? d_q : (blockIdx.z == 1) ? d_kk : d_v;
    float acc[4][4];
    gemm_nt_core(d_gn1, W, KDIM, m0, n0, acc);
    const int tx = threadIdx.x & 15, ty = threadIdx.x >> 4;
#pragma unroll
    for (int i = 0; i < 4; i++)
#pragma unroll
        for (int j = 0; j < 4; j++)
            C[(size_t)(m0 + ty * 4 + i) * KDIM + n0 + tx * 4 + j] = acc[i][j];
}

// scores[b,t,s] = (q_t . k_s) * (1/16) * decay^(s-t-1) for s>t else 0.  grid(8,8,2)
__global__ void k_scores(const float* __restrict__ p_dl)
{
    const int b  = blockIdx.z;
    const int m0 = blockIdx.y * 64;   // t
    const int n0 = blockIdx.x * 64;   // s
    if (n0 + 63 <= m0) return;        // entire tile has s <= t -> zero, never read downstream
    const float* A = d_q  + (size_t)b * TSEQ * KDIM;
    const float* B = d_kk + (size_t)b * TSEQ * KDIM;
    float acc[4][4];
    gemm_nt_core(A, B, KDIM, m0, n0, acc);
    const float dl = *p_dl;
    const float decay = 1.f / (1.f + expf(-dl));
    const float l2d = log2f(decay);
    float* C = d_scores + (size_t)b * TSEQ * TSEQ;
    const int tx = threadIdx.x & 15, ty = threadIdx.x >> 4;
#pragma unroll
    for (int i = 0; i < 4; i++) {
        const int t = m0 + ty * 4 + i;
#pragma unroll
        for (int j = 0; j < 4; j++) {
            const int s = n0 + tx * 4 + j;
            float w = (s > t) ? exp2f((float)(s - t - 1) * l2d) : 0.f;
            C[(size_t)t * TSEQ + s] = acc[i][j] * 0.0625f * w;
        }
    }
}

// retrieved[b] = scores[b] @ v[b]   grid(4,8,2); skip k-tiles fully below diagonal
__global__ void k_retr()
{
    const int b  = blockIdx.z;
    const int m0 = blockIdx.y * 64;
    const int n0 = blockIdx.x * 64;
    const float* A = d_scores + (size_t)b * TSEQ * TSEQ;
    const float* B = d_v + (size_t)b * TSEQ * KDIM;
    float acc[4][4];
    gemm_nn_core(A, B, TSEQ, KDIM, m0, n0, /*kstart=*/m0, acc);
    const int tx = threadIdx.x & 15, ty = threadIdx.x >> 4;
#pragma unroll
    for (int i = 0; i < 4; i++)
#pragma unroll
        for (int j = 0; j < 4; j++)
            d_retr[(size_t)(b * TSEQ + m0 + ty * 4 + i) * KDIM + n0 + tx * 4 + j] = acc[i][j];
}

// g2 = gathered + mem_scale * (retr @ Wo^T * out_scale)  grid(4,16)
__global__ void k_wo(const float* __restrict__ Wo, const float* __restrict__ p_os,
                     const float* __restrict__ p_ms)
{
    const int m0 = blockIdx.y * 64, n0 = blockIdx.x * 64;
    float acc[4][4];
    gemm_nt_core(d_retr, Wo, KDIM, m0, n0, acc);
    const float os = *p_os, ms = *p_ms;
    const int tx = threadIdx.x & 15, ty = threadIdx.x >> 4;
#pragma unroll
    for (int i = 0; i < 4; i++)
#pragma unroll
        for (int j = 0; j < 4; j++) {
            size_t idx = (size_t)(m0 + ty * 4 + i) * KDIM + n0 + tx * 4 + j;
            d_g2[idx] = d_gathered[idx] + ms * (acc[i][j] * os);
        }
}

// h = gelu(gn2 @ Wdown^T + bias)  grid(8,16)
__global__ void k_down(const float* __restrict__ Wdown, const float* __restrict__ bias)
{
    const int m0 = blockIdx.y * 64, n0 = blockIdx.x * 64;
    float acc[4][4];
    gemm_nt_core(d_gn2, Wdown, KDIM, m0, n0, acc);
    const int tx = threadIdx.x & 15, ty = threadIdx.x >> 4;
#pragma unroll
    for (int i = 0; i < 4; i++)
#pragma unroll
        for (int j = 0; j < 4; j++) {
            const int n = n0 + tx * 4 + j;
            float hv = acc[i][j] + bias[n];
            float g = 0.5f * hv * (1.f + erff(hv * 0.70710678118654752f));
            d_h[(size_t)(m0 + ty * 4 + i) * INNERD + n] = g;
        }
}

// mlpout = h @ Wup^T   grid(4,16)
__global__ void k_up(const float* __restrict__ Wup)
{
    const int m0 = blockIdx.y * 64, n0 = blockIdx.x * 64;
    float acc[4][4];
    gemm_nt_core(d_h, Wup, INNERD, m0, n0, acc);
    const int tx = threadIdx.x & 15, ty = threadIdx.x >> 4;
#pragma unroll
    for (int i = 0; i < 4; i++)
#pragma unroll
        for (int j = 0; j < 4; j++)
            d_mlp[(size_t)(m0 + ty * 4 + i) * KDIM + n0 + tx * 4 + j] = acc[i][j];
}

// ---------------- final big kernel ----------------
// One CTA per (b,t) row. Row staged in SMEM. entropy -> delta scatter -> radix top-128 -> masked write.
#define FTPB 1024
// smem floats: y[32000] | hist(int)[256] | eq(int)[512] | sel(int)[128] | red[32] | sint(int)[8]
#define SM_Y      0
#define SM_HIST   32000
#define SM_EQ     (32000 + 256)
#define SM_SEL    (32000 + 256 + 512)
#define SM_RED    (32000 + 256 + 512 + 128)
#define SM_SINT   (32000 + 256 + 512 + 128 + 32)
#define SM_TOTALF (32000 + 256 + 512 + 128 + 32 + 8)
#define FINAL_SMEM_BYTES (SM_TOTALF * 4)

__device__ __forceinline__ float blockReduceSumF(float v, float* red)
{
#pragma unroll
    for (int o = 16; o; o >>= 1) v += __shfl_xor_sync(0xffffffffu, v, o);
    const int w = threadIdx.x >> 5, l = threadIdx.x & 31;
    if (l == 0) red[w] = v;
    __syncthreads();
    if (w == 0) {
        v = red[l];
#pragma unroll
        for (int o = 16; o; o >>= 1) v += __shfl_xor_sync(0xffffffffu, v, o);
        if (l == 0) red[0] = v;
    }
    __syncthreads();
    float r = red[0];
    __syncthreads();
    return r;
}

__device__ __forceinline__ float blockReduceMaxF(float v, float* red)
{
#pragma unroll
    for (int o = 16; o; o >>= 1) v = fmaxf(v, __shfl_xor_sync(0xffffffffu, v, o));
    const int w = threadIdx.x >> 5, l = threadIdx.x & 31;
    if (l == 0) red[w] = v;
    __syncthreads();
    if (w == 0) {
        v = red[l];
#pragma unroll
        for (int o = 16; o; o >>= 1) v = fmaxf(v, __shfl_xor_sync(0xffffffffu, v, o));
        if (l == 0) red[0] = v;
    }
    __syncthreads();
    float r = red[0];
    __syncthreads();
    return r;
}

__global__ void k_final(const float* __restrict__ x, const int* __restrict__ widx,
                        const float* __restrict__ p_ws, float* __restrict__ out)
{
    extern __shared__ __align__(16) float smem[];
    float* y    = smem + SM_Y;
    int*   hist = (int*)(smem + SM_HIST);
    int*   eq   = (int*)(smem + SM_EQ);
    int*   sel  = (int*)(smem + SM_SEL);
    float* red  = smem + SM_RED;
    int*   sint = (int*)(smem + SM_SINT);

    const int row = blockIdx.x;
    const int tid = threadIdx.x;
    const float* xr = x + (size_t)row * VDIM;
    float* outr = out + (size_t)row * VDIM;

    // load + running max
    float lmax = __int_as_float(0xff800000);  // -inf
    const float4* x4 = (const float4*)xr;
    float4* y4 = (float4*)y;
    for (int i = tid; i < VDIM / 4; i += FTPB) {
        float4 v = x4[i];
        y4[i] = v;
        lmax = fmaxf(lmax, fmaxf(fmaxf(v.x, v.y), fmaxf(v.z, v.w)));
    }
    __syncthreads();
    const float mx = blockReduceMaxF(lmax, red);

    // sumexp
    float lsum = 0.f;
    for (int i = tid; i < VDIM; i += FTPB) lsum += expf(y[i] - mx);
    const float S = blockReduceSumF(lsum, red);
    const float lse = mx + logf(S);

    // entropy = -sum p*log(p+1e-8)
    float lent = 0.f;
    for (int i = tid; i < VDIM; i += FTPB) {
        float p = expf(y[i] - lse);
        lent += p * logf(p + 1e-8f);
    }
    const float E = blockReduceSumF(lent, red);
    const float escale = (-E) / logf((float)VDIM);

    // delta scatter (entropy computed on original x, so apply after)
    const float coef = (*p_ws) * 0.0625f * escale;  // write_scale * 1/sqrt(K) * entropy_scale
    if (tid < KDIM) {
        int c = widx[tid];
        atomicAdd(&y[c], d_mlp[(size_t)row * KDIM + tid] * coef);
    }
    __syncthreads();

    // radix select: exact 128th-largest key of |y|
    unsigned thresh = 0u;
    int need = SPARSE_K;
    for (int pass = 0; pass < 4; ++pass) {
        const int shift = 24 - 8 * pass;
        for (int i = tid; i < 256; i += FTPB) hist[i] = 0;
        __syncthreads();
        const unsigned pmask = (pass == 0) ? 0u : (0xFFFFFFFFu << (shift + 8));
        for (int i = tid; i < VDIM; i += FTPB) {
            unsigned key = __float_as_uint(fabsf(y[i]));
            if ((key & pmask) == thresh)
                atomicAdd(&hist[(key >> shift) & 255], 1);
        }
        __syncthreads();
        if (tid == 0) {
            int cum = 0, b = 255;
            for (; b >= 0; --b) { cum += hist[b]; if (cum >= need) break; }
            sint[0] = b;
            sint[1] = need - (cum - hist[b]);
        }
        __syncthreads();
        thresh |= ((unsigned)sint[0]) << shift;
        need = sint[1];
        __syncthreads();
    }

    // collect ties at threshold
    if (tid == 0) sint[2] = 0;
    __syncthreads();
    for (int i = tid; i < VDIM; i += FTPB) {
        unsigned key = __float_as_uint(fabsf(y[i]));
        if (key == thresh) {
            int p = atomicAdd(&sint[2], 1);
            if (p < 512) eq[p] = i;
        }
    }
    __syncthreads();
    const int neq = sint[2];
    const int keepEq = need;
    const bool allEq = (neq <= keepEq);
    if (!allEq) {
        if (tid == 0) {
            int cnt = neq < 512 ? neq : 512;
            for (int r = 0; r < keepEq; ++r) {
                int best = 0x7fffffff, bj = 0;
                for (int j = 0; j < cnt; ++j)
                    if (eq[j] < best) { best = eq[j]; bj = j; }
                sel[r] = best;
                eq[bj] = 0x7fffffff;
            }
        }
        __syncthreads();
    }

    // masked write
    float4* out4 = (float4*)outr;
    for (int i4 = tid; i4 < VDIM / 4; i4 += FTPB) {
        float4 v = y4[i4];
        float o[4] = {v.x, v.y, v.z, v.w};
#pragma unroll
        for (int j = 0; j < 4; j++) {
            unsigned key = __float_as_uint(fabsf(o[j]));
            bool keep = key > thresh;
            if (!keep && key == thresh) {
                if (allEq) keep = true;
                else {
                    int idx = i4 * 4 + j;
                    for (int r = 0; r < keepEq; ++r)
                        if (sel[r] == idx) { keep = true; break; }
                }
            }
            if (!keep) o[j] = 0.f;
        }
        out4[i4] = make_float4(o[0], o[1], o[2], o[3]);
    }
}

// ---------------- launch ----------------
extern "C" void kernel_launch(void* const* d_in, const int* in_sizes, int n_in,
                              void* d_out, int out_size)
{
    const float* x      = (const float*)d_in[0];
    const float* Wq     = (const float*)d_in[1];
    const float* Wk     = (const float*)d_in[2];
    const float* Wv     = (const float*)d_in[3];
    const float* Wo     = (const float*)d_in[4];
    const float* dl     = (const float*)d_in[5];
    const float* os     = (const float*)d_in[6];
    const float* ms     = (const float*)d_in[7];
    const float* ws     = (const float*)d_in[8];
    const float* Wdown  = (const float*)d_in[9];
    const float* Wup    = (const float*)d_in[10];
    const float* bias   = (const float*)d_in[11];
    const int*   ridx   = (const int*)d_in[12];
    const int*   widx   = (const int*)d_in[13];
    float* out = (float*)d_out;

    k_gather_rms<<<BT_ROWS, KDIM>>>(x, ridx);
    k_qkv<<<dim3(KDIM / 64, BT_ROWS / 64, 3), 256>>>(Wq, Wk, Wv);
    k_scores<<<dim3(TSEQ / 64, TSEQ / 64, NBATCH), 256>>>(dl);
    k_retr<<<dim3(KDIM / 64, TSEQ / 64, NBATCH), 256>>>();
    k_wo<<<dim3(KDIM / 64, BT_ROWS / 64), 256>>>(Wo, os, ms);
    k_rms2<<<BT_ROWS, KDIM>>>();
    k_down<<<dim3(INNERD / 64, BT_ROWS / 64), 256>>>(Wdown, bias);
    k_up<<<dim3(KDIM / 64, BT_ROWS / 64), 256>>>(Wup);

    cudaFuncSetAttribute(k_final, cudaFuncAttributeMaxDynamicSharedMemorySize,
                         FINAL_SMEM_BYTES);
    k_final<<<BT_ROWS, FTPB, FINAL_SMEM_BYTES>>>(x, widx, ws, out);
}

// round 3
// speedup vs baseline: 1.0949x; 1.0949x over previous
#include <cuda_runtime.h>
#include <math.h>

// Problem constants
#define BT_ROWS 1024     // B*T
#define KDIM    256
#define TSEQ    512
#define VDIM    32000
#define INNERD  512
#define NBATCH  2
#define SPARSE_K 128
#define EPS_F   1.1920929e-7f

// ---------------- scratch buffers ----------------
__device__ __align__(16) float d_gathered[BT_ROWS * KDIM];
__device__ __align__(16) float d_gn1[BT_ROWS * KDIM];
__device__ __align__(16) float d_gn2[BT_ROWS * KDIM];
__device__ __align__(16) float d_qkvp[6 * BT_ROWS * KDIM];        // [mat*2+split]
__device__ __align__(16) float d_scoresp[2 * NBATCH * TSEQ * TSEQ]; // [split]
__device__ __align__(16) float d_retrp[4 * BT_ROWS * KDIM];       // [split]
__device__ __align__(16) float d_wop[4 * BT_ROWS * KDIM];         // [split]
__device__ __align__(16) float d_hp[2 * BT_ROWS * INNERD];        // [split]
__device__ __align__(16) float d_hact[BT_ROWS * INNERD];
__device__ __align__(16) float d_mlpp[4 * BT_ROWS * KDIM];        // [split]

__device__ __forceinline__ float4 ld4(const float* p) { return *(const float4*)p; }

// ---------------- GEMM tile core ----------------
// 64x64 output tile, 128 threads, 4x8 micro-tile, K in chunks of 16.
// NT variant: loaders la(r,k), lb(r,k) give A[m0+r][k], B[n0+r][k] (both stored k-major in smem).
#define SMS 68

template <class FA, class FB>
__device__ __forceinline__ void gemm_tile_nt(FA la, FB lb, int kbeg, int kend, float acc[4][8])
{
    __shared__ float As[16 * SMS];
    __shared__ float Bs[16 * SMS];
    const int tid = threadIdx.x;
    const int lr  = tid >> 2;          // 0..31
    const int lc  = (tid & 3) << 2;    // 0,4,8,12
    const int tx  = tid & 7;
    const int ty  = tid >> 3;

#pragma unroll
    for (int i = 0; i < 4; i++)
#pragma unroll
        for (int j = 0; j < 8; j++) acc[i][j] = 0.f;

    for (int k0 = kbeg; k0 < kend; k0 += 16) {
        float4 a0 = la(lr, k0 + lc);
        float4 a1 = la(lr + 32, k0 + lc);
        float4 b0 = lb(lr, k0 + lc);
        float4 b1 = lb(lr + 32, k0 + lc);
        __syncthreads();
        As[(lc+0)*SMS + lr] = a0.x; As[(lc+1)*SMS + lr] = a0.y;
        As[(lc+2)*SMS + lr] = a0.z; As[(lc+3)*SMS + lr] = a0.w;
        As[(lc+0)*SMS + lr+32] = a1.x; As[(lc+1)*SMS + lr+32] = a1.y;
        As[(lc+2)*SMS + lr+32] = a1.z; As[(lc+3)*SMS + lr+32] = a1.w;
        Bs[(lc+0)*SMS + lr] = b0.x; Bs[(lc+1)*SMS + lr] = b0.y;
        Bs[(lc+2)*SMS + lr] = b0.z; Bs[(lc+3)*SMS + lr] = b0.w;
        Bs[(lc+0)*SMS + lr+32] = b1.x; Bs[(lc+1)*SMS + lr+32] = b1.y;
        Bs[(lc+2)*SMS + lr+32] = b1.z; Bs[(lc+3)*SMS + lr+32] = b1.w;
        __syncthreads();
#pragma unroll
        for (int kk = 0; kk < 16; ++kk) {
            float4 av  = *(const float4*)&As[kk*SMS + ty*4];
            float4 bv0 = *(const float4*)&Bs[kk*SMS + tx*8];
            float4 bv1 = *(const float4*)&Bs[kk*SMS + tx*8 + 4];
            float a_[4] = {av.x, av.y, av.z, av.w};
            float b_[8] = {bv0.x, bv0.y, bv0.z, bv0.w, bv1.x, bv1.y, bv1.z, bv1.w};
#pragma unroll
            for (int i = 0; i < 4; i++)
#pragma unroll
                for (int j = 0; j < 8; j++) acc[i][j] += a_[i] * b_[j];
        }
    }
}

// NN variant: la(r,k) -> A[m0+r][k] (transposed to k-major smem),
//             lbk(kr,c) -> B[kr][n0+c..c+3] as float4 (stored direct).
template <class FA, class FBK>
__device__ __forceinline__ void gemm_tile_nn(FA la, FBK lbk, int kbeg, int kend, float acc[4][8])
{
    __shared__ float As[16 * SMS];
    __shared__ float Bs[16 * SMS];
    const int tid = threadIdx.x;
    const int lr  = tid >> 2;          // 0..31
    const int lc  = (tid & 3) << 2;    // 0,4,8,12
    const int kr  = tid >> 4;          // 0..7
    const int bc  = (tid & 15) << 2;   // 0..60
    const int tx  = tid & 7;
    const int ty  = tid >> 3;

#pragma unroll
    for (int i = 0; i < 4; i++)
#pragma unroll
        for (int j = 0; j < 8; j++) acc[i][j] = 0.f;

    for (int k0 = kbeg; k0 < kend; k0 += 16) {
        float4 a0 = la(lr, k0 + lc);
        float4 a1 = la(lr + 32, k0 + lc);
        float4 bb0 = lbk(k0 + kr, bc);
        float4 bb1 = lbk(k0 + kr + 8, bc);
        __syncthreads();
        As[(lc+0)*SMS + lr] = a0.x; As[(lc+1)*SMS + lr] = a0.y;
        As[(lc+2)*SMS + lr] = a0.z; As[(lc+3)*SMS + lr] = a0.w;
        As[(lc+0)*SMS + lr+32] = a1.x; As[(lc+1)*SMS + lr+32] = a1.y;
        As[(lc+2)*SMS + lr+32] = a1.z; As[(lc+3)*SMS + lr+32] = a1.w;
        *(float4*)&Bs[kr*SMS + bc] = bb0;
        *(float4*)&Bs[(kr+8)*SMS + bc] = bb1;
        __syncthreads();
#pragma unroll
        for (int kk = 0; kk < 16; ++kk) {
            float4 av  = *(const float4*)&As[kk*SMS + ty*4];
            float4 bv0 = *(const float4*)&Bs[kk*SMS + tx*8];
            float4 bv1 = *(const float4*)&Bs[kk*SMS + tx*8 + 4];
            float a_[4] = {av.x, av.y, av.z, av.w};
            float b_[8] = {bv0.x, bv0.y, bv0.z, bv0.w, bv1.x, bv1.y, bv1.z, bv1.w};
#pragma unroll
            for (int i = 0; i < 4; i++)
#pragma unroll
                for (int j = 0; j < 8; j++) acc[i][j] += a_[i] * b_[j];
        }
    }
}

// ---------------- stage kernels ----------------

// gather + rmsnorm
__global__ void k_gather_rms(const float* __restrict__ x, const int* __restrict__ ridx)
{
    const int row = blockIdx.x;
    const int tid = threadIdx.x;
    float g = x[(size_t)row * VDIM + ridx[tid]];
    d_gathered[row * KDIM + tid] = g;
    __shared__ float red[8];
    float s = g * g;
#pragma unroll
    for (int o = 16; o; o >>= 1) s += __shfl_xor_sync(0xffffffffu, s, o);
    if ((tid & 31) == 0) red[tid >> 5] = s;
    __syncthreads();
    if (tid < 32) {
        float v = (tid < 8) ? red[tid] : 0.f;
#pragma unroll
        for (int o = 4; o; o >>= 1) v += __shfl_xor_sync(0xffffffffu, v, o);
        if (tid == 0) red[0] = v;
    }
    __syncthreads();
    float r = rsqrtf(red[0] * (1.f / KDIM) + EPS_F);
    d_gn1[row * KDIM + tid] = g * r;
}

// qkv projections, split-K2: z = mat*2 + split
__global__ void __launch_bounds__(128) k_qkv(
    const float* __restrict__ Wq, const float* __restrict__ Wk, const float* __restrict__ Wv)
{
    const int n0 = blockIdx.x * 64, m0 = blockIdx.y * 64;
    const int mat = blockIdx.z >> 1, split = blockIdx.z & 1;
    const float* W = (mat == 0) ? Wq : (mat == 1) ? Wk : Wv;
    float* C = d_qkvp + (size_t)blockIdx.z * BT_ROWS * KDIM;
    float acc[4][8];
    auto la = [&](int r, int k) { return ld4(&d_gn1[(size_t)(m0 + r) * KDIM + k]); };
    auto lb = [&](int r, int k) { return ld4(&W[(size_t)(n0 + r) * KDIM + k]); };
    gemm_tile_nt(la, lb, split * 128, split * 128 + 128, acc);
    const int tx = threadIdx.x & 7, ty = threadIdx.x >> 3;
#pragma unroll
    for (int i = 0; i < 4; i++)
#pragma unroll
        for (int j = 0; j < 8; j++)
            C[(size_t)(m0 + ty*4 + i) * KDIM + n0 + tx*8 + j] = acc[i][j];
}

// raw scores = q . k  (split-K2); z = b*2 + split
__global__ void __launch_bounds__(128) k_scores()
{
    const int n0 = blockIdx.x * 64;    // s
    const int m0 = blockIdx.y * 64;    // t
    if (n0 + 63 <= m0) return;         // fully below/at diagonal -> never read with nonzero weight
    const int b = blockIdx.z >> 1, split = blockIdx.z & 1;
    const float* q0 = d_qkvp + (size_t)0 * BT_ROWS * KDIM + (size_t)b * TSEQ * KDIM;
    const float* q1 = d_qkvp + (size_t)1 * BT_ROWS * KDIM + (size_t)b * TSEQ * KDIM;
    const float* k0p = d_qkvp + (size_t)2 * BT_ROWS * KDIM + (size_t)b * TSEQ * KDIM;
    const float* k1p = d_qkvp + (size_t)3 * BT_ROWS * KDIM + (size_t)b * TSEQ * KDIM;
    float acc[4][8];
    auto la = [&](int r, int k) {
        float4 u = ld4(&q0[(size_t)(m0 + r) * KDIM + k]);
        float4 v = ld4(&q1[(size_t)(m0 + r) * KDIM + k]);
        return make_float4(u.x+v.x, u.y+v.y, u.z+v.z, u.w+v.w);
    };
    auto lb = [&](int r, int k) {
        float4 u = ld4(&k0p[(size_t)(n0 + r) * KDIM + k]);
        float4 v = ld4(&k1p[(size_t)(n0 + r) * KDIM + k]);
        return make_float4(u.x+v.x, u.y+v.y, u.z+v.z, u.w+v.w);
    };
    gemm_tile_nt(la, lb, split * 128, split * 128 + 128, acc);
    float* C = d_scoresp + (size_t)split * NBATCH * TSEQ * TSEQ + (size_t)b * TSEQ * TSEQ;
    const int tx = threadIdx.x & 7, ty = threadIdx.x >> 3;
#pragma unroll
    for (int i = 0; i < 4; i++)
#pragma unroll
        for (int j = 0; j < 8; j++)
            C[(size_t)(m0 + ty*4 + i) * TSEQ + n0 + tx*8 + j] = acc[i][j];
}

// retrieved = (weighted scores) @ v   split-4 over s-range [m0,512); z = b*4 + split
__global__ void __launch_bounds__(128) k_retr(const float* __restrict__ p_dl)
{
    const int n0 = blockIdx.x * 64;
    const int m0 = blockIdx.y * 64;
    const int b = blockIdx.z >> 2, split = blockIdx.z & 3;
    const int len = (TSEQ - m0) >> 2;          // multiple of 16
    const int kbeg = m0 + split * len, kend = kbeg + len;
    const float dl = *p_dl;
    const float decay = 1.f / (1.f + expf(-dl));
    const float l2d = log2f(decay);
    const float* s0 = d_scoresp + (size_t)b * TSEQ * TSEQ;
    const float* s1 = d_scoresp + (size_t)NBATCH * TSEQ * TSEQ + (size_t)b * TSEQ * TSEQ;
    const float* v0 = d_qkvp + (size_t)4 * BT_ROWS * KDIM + (size_t)b * TSEQ * KDIM;
    const float* v1 = d_qkvp + (size_t)5 * BT_ROWS * KDIM + (size_t)b * TSEQ * KDIM;
    float acc[4][8];
    auto la = [&](int r, int k) {   // weighted scores row t=m0+r, cols s=k..k+3
        const int t = m0 + r;
        float4 u = ld4(&s0[(size_t)t * TSEQ + k]);
        float4 v = ld4(&s1[(size_t)t * TSEQ + k]);
        float o[4] = {u.x+v.x, u.y+v.y, u.z+v.z, u.w+v.w};
#pragma unroll
        for (int j = 0; j < 4; j++) {
            int s = k + j;
            float w = (s > t) ? 0.0625f * exp2f((float)(s - t - 1) * l2d) : 0.f;
            o[j] *= w;
        }
        return make_float4(o[0], o[1], o[2], o[3]);
    };
    auto lbk = [&](int kr, int c) {  // v row s=kr, cols n0+c..+3
        float4 u = ld4(&v0[(size_t)kr * KDIM + n0 + c]);
        float4 v = ld4(&v1[(size_t)kr * KDIM + n0 + c]);
        return make_float4(u.x+v.x, u.y+v.y, u.z+v.z, u.w+v.w);
    };
    gemm_tile_nn(la, lbk, kbeg, kend, acc);
    float* C = d_retrp + (size_t)split * BT_ROWS * KDIM + (size_t)b * TSEQ * KDIM;
    const int tx = threadIdx.x & 7, ty = threadIdx.x >> 3;
#pragma unroll
    for (int i = 0; i < 4; i++)
#pragma unroll
        for (int j = 0; j < 8; j++)
            C[(size_t)(m0 + ty*4 + i) * KDIM + n0 + tx*8 + j] = acc[i][j];
}

// wo partials = retr @ Wo^T, split-K4; z = split
__global__ void __launch_bounds__(128) k_wo(const float* __restrict__ Wo)
{
    const int n0 = blockIdx.x * 64, m0 = blockIdx.y * 64;
    const int split = blockIdx.z;
    float acc[4][8];
    auto la = [&](int r, int k) {
        size_t off = (size_t)(m0 + r) * KDIM + k;
        float4 a = ld4(&d_retrp[off]);
        float4 b = ld4(&d_retrp[(size_t)BT_ROWS*KDIM + off]);
        float4 c = ld4(&d_retrp[(size_t)2*BT_ROWS*KDIM + off]);
        float4 d = ld4(&d_retrp[(size_t)3*BT_ROWS*KDIM + off]);
        return make_float4(a.x+b.x+c.x+d.x, a.y+b.y+c.y+d.y, a.z+b.z+c.z+d.z, a.w+b.w+c.w+d.w);
    };
    auto lb = [&](int r, int k) { return ld4(&Wo[(size_t)(n0 + r) * KDIM + k]); };
    gemm_tile_nt(la, lb, split * 64, split * 64 + 64, acc);
    float* C = d_wop + (size_t)split * BT_ROWS * KDIM;
    const int tx = threadIdx.x & 7, ty = threadIdx.x >> 3;
#pragma unroll
    for (int i = 0; i < 4; i++)
#pragma unroll
        for (int j = 0; j < 8; j++)
            C[(size_t)(m0 + ty*4 + i) * KDIM + n0 + tx*8 + j] = acc[i][j];
}

// g2 = gathered + ms*os*(sum of wo partials); rmsnorm -> gn2
__global__ void k_rms2(const float* __restrict__ p_os, const float* __restrict__ p_ms)
{
    const int row = blockIdx.x;
    const int tid = threadIdx.x;
    const size_t idx = (size_t)row * KDIM + tid;
    float wsum = d_wop[idx] + d_wop[(size_t)BT_ROWS*KDIM + idx]
               + d_wop[(size_t)2*BT_ROWS*KDIM + idx] + d_wop[(size_t)3*BT_ROWS*KDIM + idx];
    float g = d_gathered[idx] + (*p_ms) * ((*p_os) * wsum);
    __shared__ float red[8];
    float s = g * g;
#pragma unroll
    for (int o = 16; o; o >>= 1) s += __shfl_xor_sync(0xffffffffu, s, o);
    if ((tid & 31) == 0) red[tid >> 5] = s;
    __syncthreads();
    if (tid < 32) {
        float v = (tid < 8) ? red[tid] : 0.f;
#pragma unroll
        for (int o = 4; o; o >>= 1) v += __shfl_xor_sync(0xffffffffu, v, o);
        if (tid == 0) red[0] = v;
    }
    __syncthreads();
    float r = rsqrtf(red[0] * (1.f / KDIM) + EPS_F);
    d_gn2[idx] = g * r;
}

// down partials = gn2 @ Wdown^T, split-K2
__global__ void __launch_bounds__(128) k_down(const float* __restrict__ Wdown)
{
    const int n0 = blockIdx.x * 64, m0 = blockIdx.y * 64;
    const int split = blockIdx.z;
    float acc[4][8];
    auto la = [&](int r, int k) { return ld4(&d_gn2[(size_t)(m0 + r) * KDIM + k]); };
    auto lb = [&](int r, int k) { return ld4(&Wdown[(size_t)(n0 + r) * KDIM + k]); };
    gemm_tile_nt(la, lb, split * 128, split * 128 + 128, acc);
    float* C = d_hp + (size_t)split * BT_ROWS * INNERD;
    const int tx = threadIdx.x & 7, ty = threadIdx.x >> 3;
#pragma unroll
    for (int i = 0; i < 4; i++)
#pragma unroll
        for (int j = 0; j < 8; j++)
            C[(size_t)(m0 + ty*4 + i) * INNERD + n0 + tx*8 + j] = acc[i][j];
}

// hact = gelu(hp0 + hp1 + bias)
__global__ void k_gelu(const float* __restrict__ bias)
{
    const int i = blockIdx.x * blockDim.x + threadIdx.x;
    float h = d_hp[i] + d_hp[(size_t)BT_ROWS * INNERD + i] + bias[i & (INNERD - 1)];
    d_hact[i] = 0.5f * h * (1.f + erff(h * 0.70710678118654752f));
}

// mlp partials = hact @ Wup^T, split-K4
__global__ void __launch_bounds__(128) k_up(const float* __restrict__ Wup)
{
    const int n0 = blockIdx.x * 64, m0 = blockIdx.y * 64;
    const int split = blockIdx.z;
    float acc[4][8];
    auto la = [&](int r, int k) { return ld4(&d_hact[(size_t)(m0 + r) * INNERD + k]); };
    auto lb = [&](int r, int k) { return ld4(&Wup[(size_t)(n0 + r) * INNERD + k]); };
    gemm_tile_nt(la, lb, split * 128, split * 128 + 128, acc);
    float* C = d_mlpp + (size_t)split * BT_ROWS * KDIM;
    const int tx = threadIdx.x & 7, ty = threadIdx.x >> 3;
#pragma unroll
    for (int i = 0; i < 4; i++)
#pragma unroll
        for (int j = 0; j < 8; j++)
            C[(size_t)(m0 + ty*4 + i) * KDIM + n0 + tx*8 + j] = acc[i][j];
}

// ---------------- final big kernel ----------------
#define FTPB 1024
#define SM_Y      0
#define SM_HIST   32000
#define SM_EQ     (32000 + 256)
#define SM_SEL    (32000 + 256 + 512)
#define SM_RED    (32000 + 256 + 512 + 128)
#define SM_SINT   (32000 + 256 + 512 + 128 + 32)
#define SM_TOTALF (32000 + 256 + 512 + 128 + 32 + 8)
#define FINAL_SMEM_BYTES (SM_TOTALF * 4)

__device__ __forceinline__ float blockReduceSumF(float v, float* red)
{
#pragma unroll
    for (int o = 16; o; o >>= 1) v += __shfl_xor_sync(0xffffffffu, v, o);
    const int w = threadIdx.x >> 5, l = threadIdx.x & 31;
    if (l == 0) red[w] = v;
    __syncthreads();
    if (w == 0) {
        v = red[l];
#pragma unroll
        for (int o = 16; o; o >>= 1) v += __shfl_xor_sync(0xffffffffu, v, o);
        if (l == 0) red[0] = v;
    }
    __syncthreads();
    float r = red[0];
    __syncthreads();
    return r;
}

__device__ __forceinline__ float blockReduceMaxF(float v, float* red)
{
#pragma unroll
    for (int o = 16; o; o >>= 1) v = fmaxf(v, __shfl_xor_sync(0xffffffffu, v, o));
    const int w = threadIdx.x >> 5, l = threadIdx.x & 31;
    if (l == 0) red[w] = v;
    __syncthreads();
    if (w == 0) {
        v = red[l];
#pragma unroll
        for (int o = 16; o; o >>= 1) v = fmaxf(v, __shfl_xor_sync(0xffffffffu, v, o));
        if (l == 0) red[0] = v;
    }
    __syncthreads();
    float r = red[0];
    __syncthreads();
    return r;
}

__global__ void k_final(const float* __restrict__ x, const int* __restrict__ widx,
                        const float* __restrict__ p_ws, float* __restrict__ out)
{
    extern __shared__ __align__(16) float smem[];
    float* y    = smem + SM_Y;
    int*   hist = (int*)(smem + SM_HIST);
    int*   eq   = (int*)(smem + SM_EQ);
    int*   sel  = (int*)(smem + SM_SEL);
    float* red  = smem + SM_RED;
    int*   sint = (int*)(smem + SM_SINT);

    const int row = blockIdx.x;
    const int tid = threadIdx.x;
    const float* xr = x + (size_t)row * VDIM;
    float* outr = out + (size_t)row * VDIM;

    float lmax = __int_as_float(0xff800000);
    const float4* x4 = (const float4*)xr;
    float4* y4 = (float4*)y;
    for (int i = tid; i < VDIM / 4; i += FTPB) {
        float4 v = x4[i];
        y4[i] = v;
        lmax = fmaxf(lmax, fmaxf(fmaxf(v.x, v.y), fmaxf(v.z, v.w)));
    }
    __syncthreads();
    const float mx = blockReduceMaxF(lmax, red);

    float lsum = 0.f;
    for (int i = tid; i < VDIM; i += FTPB) lsum += expf(y[i] - mx);
    const float S = blockReduceSumF(lsum, red);
    const float lse = mx + logf(S);

    float lent = 0.f;
    for (int i = tid; i < VDIM; i += FTPB) {
        float p = expf(y[i] - lse);
        lent += p * logf(p + 1e-8f);
    }
    const float E = blockReduceSumF(lent, red);
    const float escale = (-E) / logf((float)VDIM);

    const float coef = (*p_ws) * 0.0625f * escale;
    if (tid < KDIM) {
        const size_t off = (size_t)row * KDIM + tid;
        float m = d_mlpp[off] + d_mlpp[(size_t)BT_ROWS*KDIM + off]
                + d_mlpp[(size_t)2*BT_ROWS*KDIM + off] + d_mlpp[(size_t)3*BT_ROWS*KDIM + off];
        atomicAdd(&y[widx[tid]], m * coef);
    }
    __syncthreads();

    unsigned thresh = 0u;
    int need = SPARSE_K;
    for (int pass = 0; pass < 4; ++pass) {
        const int shift = 24 - 8 * pass;
        for (int i = tid; i < 256; i += FTPB) hist[i] = 0;
        __syncthreads();
        const unsigned pmask = (pass == 0) ? 0u : (0xFFFFFFFFu << (shift + 8));
        for (int i = tid; i < VDIM; i += FTPB) {
            unsigned key = __float_as_uint(fabsf(y[i]));
            if ((key & pmask) == thresh)
                atomicAdd(&hist[(key >> shift) & 255], 1);
        }
        __syncthreads();
        if (tid == 0) {
            int cum = 0, b = 255;
            for (; b >= 0; --b) { cum += hist[b]; if (cum >= need) break; }
            sint[0] = b;
            sint[1] = need - (cum - hist[b]);
        }
        __syncthreads();
        thresh |= ((unsigned)sint[0]) << shift;
        need = sint[1];
        __syncthreads();
    }

    if (tid == 0) sint[2] = 0;
    __syncthreads();
    for (int i = tid; i < VDIM; i += FTPB) {
        unsigned key = __float_as_uint(fabsf(y[i]));
        if (key == thresh) {
            int p = atomicAdd(&sint[2], 1);
            if (p < 512) eq[p] = i;
        }
    }
    __syncthreads();
    const int neq = sint[2];
    const int keepEq = need;
    const bool allEq = (neq <= keepEq);
    if (!allEq) {
        if (tid == 0) {
            int cnt = neq < 512 ? neq : 512;
            for (int r = 0; r < keepEq; ++r) {
                int best = 0x7fffffff, bj = 0;
                for (int j = 0; j < cnt; ++j)
                    if (eq[j] < best) { best = eq[j]; bj = j; }
                sel[r] = best;
                eq[bj] = 0x7fffffff;
            }
        }
        __syncthreads();
    }

    float4* out4 = (float4*)outr;
    for (int i4 = tid; i4 < VDIM / 4; i4 += FTPB) {
        float4 v = y4[i4];
        float o[4] = {v.x, v.y, v.z, v.w};
#pragma unroll
        for (int j = 0; j < 4; j++) {
            unsigned key = __float_as_uint(fabsf(o[j]));
            bool keep = key > thresh;
            if (!keep && key == thresh) {
                if (allEq) keep = true;
                else {
                    int idx = i4 * 4 + j;
                    for (int r = 0; r < keepEq; ++r)
                        if (sel[r] == idx) { keep = true; break; }
                }
            }
            if (!keep) o[j] = 0.f;
        }
        out4[i4] = make_float4(o[0], o[1], o[2], o[3]);
    }
}

// ---------------- launch ----------------
extern "C" void kernel_launch(void* const* d_in, const int* in_sizes, int n_in,
                              void* d_out, int out_size)
{
    const float* x      = (const float*)d_in[0];
    const float* Wq     = (const float*)d_in[1];
    const float* Wk     = (const float*)d_in[2];
    const float* Wv     = (const float*)d_in[3];
    const float* Wo     = (const float*)d_in[4];
    const float* dl     = (const float*)d_in[5];
    const float* os     = (const float*)d_in[6];
    const float* ms     = (const float*)d_in[7];
    const float* ws     = (const float*)d_in[8];
    const float* Wdown  = (const float*)d_in[9];
    const float* Wup    = (const float*)d_in[10];
    const float* bias   = (const float*)d_in[11];
    const int*   ridx   = (const int*)d_in[12];
    const int*   widx   = (const int*)d_in[13];
    float* out = (float*)d_out;

    k_gather_rms<<<BT_ROWS, KDIM>>>(x, ridx);
    k_qkv<<<dim3(KDIM/64, BT_ROWS/64, 6), 128>>>(Wq, Wk, Wv);
    k_scores<<<dim3(TSEQ/64, TSEQ/64, NBATCH*2), 128>>>();
    k_retr<<<dim3(KDIM/64, TSEQ/64, NBATCH*4), 128>>>(dl);
    k_wo<<<dim3(KDIM/64, BT_ROWS/64, 4), 128>>>(Wo);
    k_rms2<<<BT_ROWS, KDIM>>>(os, ms);
    k_down<<<dim3(INNERD/64, BT_ROWS/64, 2), 128>>>(Wdown);
    k_gelu<<<(BT_ROWS*INNERD)/1024, 1024>>>(bias);
    k_up<<<dim3(KDIM/64, BT_ROWS/64, 4), 128>>>(Wup);

    cudaFuncSetAttribute(k_final, cudaFuncAttributeMaxDynamicSharedMemorySize,
                         FINAL_SMEM_BYTES);
    k_final<<<BT_ROWS, FTPB, FINAL_SMEM_BYTES>>>(x, widx, ws, out);
}